// round 12
// baseline (speedup 1.0000x reference)
#include <cuda_runtime.h>
#include <cuda_fp16.h>
#include <cstdint>

// Problem dims (fixed by the dataset)
#define BATCH 4
#define N1V   16384
#define N2V   4096
#define C1V   128
#define C2V   256
#define CINV  384      // C2 + C1 (concat order: [interp(256), features1(128)])
#define H1V   256
#define H2V   128
#define NROWS (BATCH * N1V)   // 65536

// knn candidate split
#define SPL      4
#define CAND_PER (N2V / SPL)   // 1024

// ---------------- scratch (static device globals; no runtime allocation) ---
__device__ __align__(16) int     g_idx [NROWS * 3];
__device__ __align__(16) float   g_w   [NROWS * 3];
__device__ __align__(16) float   g_ps  [(size_t)SPL * NROWS * 3];  // partial scores
__device__ __align__(16) int     g_pi  [(size_t)SPL * NROWS * 3];  // partial indices
__device__ __align__(16) __half  g_Xhi [(size_t)NROWS * CINV];
__device__ __align__(16) __half  g_Xlo [(size_t)NROWS * CINV];
__device__ __align__(16) __half  g_H   [(size_t)NROWS * H1V];   // single fp16
__device__ __align__(16) __half  g_W1  [H1V * CINV];   // [h][c] K-major, fp16
__device__ __align__(16) __half  g_W2  [H2V * H1V];    // [o][h] K-major, fp16

// ---------------------------- PTX helpers (sm_80-era, legal on sm_103) -----
__device__ __forceinline__ uint32_t smem_u32(const void* p) {
    return (uint32_t)__cvta_generic_to_shared(p);
}
__device__ __forceinline__ void cp_async16(uint32_t dst, const void* src) {
    asm volatile("cp.async.ca.shared.global [%0], [%1], 16;"
                 :: "r"(dst), "l"(src) : "memory");
}
__device__ __forceinline__ void cp_commit() {
    asm volatile("cp.async.commit_group;" ::: "memory");
}
template<int N>
__device__ __forceinline__ void cp_wait() {
    asm volatile("cp.async.wait_group %0;" :: "n"(N) : "memory");
}
__device__ __forceinline__ void ldsm_x4(uint32_t* r, uint32_t addr) {
    asm volatile("ldmatrix.sync.aligned.m8n8.x4.shared.b16 {%0,%1,%2,%3}, [%4];"
                 : "=r"(r[0]), "=r"(r[1]), "=r"(r[2]), "=r"(r[3]) : "r"(addr));
}
__device__ __forceinline__ void mma_fp16(float* d, const uint32_t* a, const uint32_t* b) {
    asm volatile(
        "mma.sync.aligned.m16n8k16.row.col.f32.f16.f16.f32 "
        "{%0,%1,%2,%3}, {%4,%5,%6,%7}, {%8,%9}, {%0,%1,%2,%3};"
        : "+f"(d[0]), "+f"(d[1]), "+f"(d[2]), "+f"(d[3])
        : "r"(a[0]), "r"(a[1]), "r"(a[2]), "r"(a[3]), "r"(b[0]), "r"(b[1]));
}

// fp16 split helpers
__device__ __forceinline__ uint32_t pack_half2(float a, float b) {
    __half2 t = __floats2half2_rn(a, b);
    return *reinterpret_cast<uint32_t*>(&t);
}
__device__ __forceinline__ float h_round(float v) {
    return __half2float(__float2half_rn(v));
}

// top-3 insert (ascending scores)
#define INS3(s, jj, S0, S1, S2, I0, I1, I2)                      \
    if ((s) < (S2)) {                                            \
        if ((s) < (S1)) {                                        \
            (S2) = (S1); (I2) = (I1);                            \
            if ((s) < (S0)) { (S1) = (S0); (I1) = (I0);          \
                              (S0) = (s);  (I0) = (jj); }        \
            else            { (S1) = (s);  (I1) = (jj); }        \
        } else { (S2) = (s); (I2) = (jj); }                      \
    }

// ---------------------------------------------------------------------------
// Kernel 1a: partial 3-NN via score s = 0.5|p|^2 - q.p (argmin-equivalent).
// QT=1 (single small tracker per thread), candidates split SPL ways across
// blockIdx.z -> 1024 CTAs, 16KB tile each => ~13 warps/SMSP (4x R9's 3.46)
// for latency hiding. grid: (N1/256, BATCH, SPL), block 256.
// ---------------------------------------------------------------------------
__global__ __launch_bounds__(256) void knn_partial_kernel(
    const float* __restrict__ xyz1, const float* __restrict__ xyz2)
{
    __shared__ float4 s2[CAND_PER];   // 16KB

    const int b     = blockIdx.y;
    const int split = blockIdx.z;
    const float* p2 = xyz2 + ((size_t)b * N2V + split * CAND_PER) * 3;
    for (int i = threadIdx.x; i < CAND_PER; i += 256) {
        const float px = p2[3 * i + 0];
        const float py = p2[3 * i + 1];
        const float pz = p2[3 * i + 2];
        const float h  = 0.5f * fmaf(pz, pz, fmaf(py, py, px * px));
        s2[i] = make_float4(px, py, pz, h);
    }
    __syncthreads();

    const int row = b * N1V + blockIdx.x * 256 + threadIdx.x;
    const float x1 = xyz1[(size_t)row * 3 + 0];
    const float y1 = xyz1[(size_t)row * 3 + 1];
    const float z1 = xyz1[(size_t)row * 3 + 2];
    const float nqx = -x1, nqy = -y1, nqz = -z1;

    float t0 = 1e30f, t1 = 1e30f, t2 = 1e30f;
    int   j0 = 0,     j1 = 0,     j2 = 0;

    #pragma unroll 8
    for (int j = 0; j < CAND_PER; j++) {
        const float4 p = s2[j];
        const float s = fmaf(nqx, p.x, fmaf(nqy, p.y, fmaf(nqz, p.z, p.w)));
        INS3(s, j, t0, t1, t2, j0, j1, j2);
    }

    const int jadd = split * CAND_PER;
    const size_t o = ((size_t)split * NROWS + row) * 3;
    g_ps[o + 0] = t0; g_ps[o + 1] = t1; g_ps[o + 2] = t2;
    g_pi[o + 0] = j0 + jadd;
    g_pi[o + 1] = j1 + jadd;
    g_pi[o + 2] = j2 + jadd;
}

// ---------------------------------------------------------------------------
// Kernel 1b: merge SPL partial top-3 lists per query (splits in index order,
// strict < => identical tie semantics to a sequential scan), then compute
// inverse-distance weights. One thread per query.
// ---------------------------------------------------------------------------
__global__ __launch_bounds__(256) void knn_merge_kernel(
    const float* __restrict__ xyz1)
{
    const int row = blockIdx.x * 256 + threadIdx.x;

    float s0 = 1e30f, s1 = 1e30f, s2 = 1e30f;
    int   i0 = 0,     i1 = 0,     i2 = 0;

    #pragma unroll
    for (int sp = 0; sp < SPL; sp++) {
        const size_t o = ((size_t)sp * NROWS + row) * 3;
        #pragma unroll
        for (int k = 0; k < 3; k++) {
            const float s = g_ps[o + k];
            const int  ii = g_pi[o + k];
            INS3(s, ii, s0, s1, s2, i0, i1, i2);
        }
    }

    const float x1 = xyz1[3 * row + 0];
    const float y1 = xyz1[3 * row + 1];
    const float z1 = xyz1[3 * row + 2];
    const float qq = fmaf(z1, z1, fmaf(y1, y1, x1 * x1));

    const float d0 = fmaxf(fmaf(2.0f, s0, qq), 1e-10f);
    const float d1 = fmaxf(fmaf(2.0f, s1, qq), 1e-10f);
    const float d2 = fmaxf(fmaf(2.0f, s2, qq), 1e-10f);
    float w0 = 1.0f / d0, w1 = 1.0f / d1, w2 = 1.0f / d2;
    const float inv = 1.0f / (w0 + w1 + w2);

    g_idx[row * 3 + 0] = i0;
    g_idx[row * 3 + 1] = i1;
    g_idx[row * 3 + 2] = i2;
    g_w[row * 3 + 0] = w0 * inv;
    g_w[row * 3 + 1] = w1 * inv;
    g_w[row * 3 + 2] = w2 * inv;
}

// ---------------------------------------------------------------------------
// Kernel 2: build X as fp16 hi/lo split:  [interp(256) | features1(128)]
// One warp per row.
// ---------------------------------------------------------------------------
__global__ __launch_bounds__(256) void build_x_kernel(
    const float* __restrict__ f1, const float* __restrict__ f2)
{
    const int gtid = blockIdx.x * blockDim.x + threadIdx.x;
    const int row  = gtid >> 5;
    const int lane = gtid & 31;
    if (row >= NROWS) return;
    const int b = row >> 14;

    const int   i0 = g_idx[row * 3 + 0];
    const int   i1 = g_idx[row * 3 + 1];
    const int   i2 = g_idx[row * 3 + 2];
    const float w0 = g_w[row * 3 + 0];
    const float w1 = g_w[row * 3 + 1];
    const float w2 = g_w[row * 3 + 2];

    const float* fb = f2 + (size_t)b * N2V * C2V;
    const float* p0 = fb + (size_t)i0 * C2V;
    const float* p1 = fb + (size_t)i1 * C2V;
    const float* p2 = fb + (size_t)i2 * C2V;

    // interp: 8 cols per lane
    const int c0 = lane * 8;
    float v[8];
    {
        float4 a0 = *(const float4*)(p0 + c0), a1 = *(const float4*)(p0 + c0 + 4);
        float4 b0 = *(const float4*)(p1 + c0), b1 = *(const float4*)(p1 + c0 + 4);
        float4 cc0 = *(const float4*)(p2 + c0), cc1 = *(const float4*)(p2 + c0 + 4);
        const float* pa = (const float*)&a0;
        const float* pb = (const float*)&b0;
        const float* pc = (const float*)&cc0;
        #pragma unroll
        for (int j = 0; j < 4; j++)
            v[j] = fmaf(w2, pc[j], fmaf(w1, pb[j], w0 * pa[j]));
        pa = (const float*)&a1; pb = (const float*)&b1; pc = (const float*)&cc1;
        #pragma unroll
        for (int j = 0; j < 4; j++)
            v[4 + j] = fmaf(w2, pc[j], fmaf(w1, pb[j], w0 * pa[j]));
    }
    uint32_t hp[4], lp[4];
    #pragma unroll
    for (int j = 0; j < 4; j++) {
        float a = v[2 * j], bb = v[2 * j + 1];
        hp[j] = pack_half2(a, bb);
        lp[j] = pack_half2(a - h_round(a), bb - h_round(bb));
    }
    __half* xh = g_Xhi + (size_t)row * CINV;
    __half* xl = g_Xlo + (size_t)row * CINV;
    *(uint4*)(xh + c0) = make_uint4(hp[0], hp[1], hp[2], hp[3]);
    *(uint4*)(xl + c0) = make_uint4(lp[0], lp[1], lp[2], lp[3]);

    // features1: 4 cols per lane
    const float4 fv = *(const float4*)(f1 + (size_t)row * C1V + lane * 4);
    uint32_t h0 = pack_half2(fv.x, fv.y);
    uint32_t h1 = pack_half2(fv.z, fv.w);
    uint32_t l0 = pack_half2(fv.x - h_round(fv.x), fv.y - h_round(fv.y));
    uint32_t l1 = pack_half2(fv.z - h_round(fv.z), fv.w - h_round(fv.w));
    *(uint2*)(xh + C2V + lane * 4) = make_uint2(h0, h1);
    *(uint2*)(xl + C2V + lane * 4) = make_uint2(l0, l1);
}

// ---------------------------------------------------------------------------
// Kernel 2b: transpose W1 (384x256 -> [256][384]) and W2 (256x128 -> [128][256])
// to K-major fp16 (single precision level — B-side quantization ~3e-4 rel).
// ---------------------------------------------------------------------------
__global__ __launch_bounds__(256) void prep_w_kernel(
    const float* __restrict__ W1, const float* __restrict__ W2)
{
    const int idx = blockIdx.x * blockDim.x + threadIdx.x;
    if (idx < CINV * H1V) {
        const int c = idx >> 8;      // / 256
        const int h = idx & 255;
        g_W1[h * CINV + c] = __float2half_rn(W1[idx]);
    } else {
        const int j = idx - CINV * H1V;
        if (j < H1V * H2V) {
            const int c = j >> 7;    // / 128
            const int h = j & 127;
            g_W2[h * H1V + c] = __float2half_rn(W2[j]);
        }
    }
}

// ---------------------------------------------------------------------------
// mma.sync fp16 GEMM:  C[M,NN] = relu( A[M,KK] * B[NN,KK]^T + bias )
// SPLIT_A=true : 2-pass D += Ahi*B + Alo*B  (A hi/lo fp16 split)
// SPLIT_A=false: 1-pass D += A*B            (A single fp16)
// fp32 accumulators. CTA 128x128, BK=32, 8 warps (2m x 4n), warp tile 64x32,
// double-buffer cp.async (2 stages). SMEM rows padded to 40 halfs (80B).
// FP16OUT: write result as single fp16 (feeds GEMM2); else fp32.
// ---------------------------------------------------------------------------
template<int NN, int KK, bool SPLIT_A, bool FP16OUT>
__global__ __launch_bounds__(256) void mma_gemm_kernel(
    const __half* __restrict__ Ahi_g, const __half* __restrict__ Alo_g,
    const __half* __restrict__ B_g,
    const float* __restrict__ bias,
    float* __restrict__ outF, __half* __restrict__ outH)
{
    constexpr int BM = 128, BK = 32;
    constexpr int NC = KK / BK;
    constexpr int NT = SPLIT_A ? 3 : 2;       // tiles per stage
    constexpr int LDS_H = 40;                 // padded halfs per smem row
    constexpr int ROWB  = LDS_H * 2;          // 80 bytes
    constexpr int TILE_B = 128 * ROWB;        // 10240 bytes per tile
    constexpr int STAGE_B = NT * TILE_B;

    extern __shared__ char smem[];
    const uint32_t sbase = smem_u32(smem);

    const int tid  = threadIdx.x;
    const int wid  = tid >> 5;
    const int lane = tid & 31;
    const int wm   = wid & 1;          // 0..1  (m)
    const int wn   = wid >> 1;         // 0..3  (n)
    const int cRow = blockIdx.x * BM;
    const int nOff = blockIdx.y * 128;

    const __half* gA[NT];
    gA[0] = Ahi_g + (size_t)cRow * KK;
    if (SPLIT_A) {
        gA[1] = Alo_g + (size_t)cRow * KK;
        gA[NT - 1] = B_g + (size_t)nOff * KK;
    } else {
        gA[NT - 1] = B_g + (size_t)nOff * KK;
    }

    // stage loader: NT tiles x 128 rows x 32 halfs (64B = 4x16B per row)
    auto load_stage = [&](int buf, int c) {
        const uint32_t s0 = sbase + buf * STAGE_B;
        #pragma unroll
        for (int t = 0; t < NT; t++) {
            const __half* g = gA[t] + c * BK;
            const uint32_t st = s0 + t * TILE_B;
            #pragma unroll
            for (int i = 0; i < 2; i++) {
                const int idx = tid + i * 256;      // 0..511
                const int r   = idx >> 2;
                const int seg = idx & 3;
                cp_async16(st + r * ROWB + seg * 16, g + (size_t)r * KK + seg * 8);
            }
        }
        cp_commit();
    };

    float acc[4][4][4] = {};   // [mt][nt][4]

    load_stage(0, 0);
    if (NC > 1) load_stage(1, 1);

    // per-lane ldmatrix base offsets
    const uint32_t aOff = (uint32_t)((wm * 64 + (lane & 15)) * ROWB + (lane >> 4) * 16);
    const uint32_t bOff = (uint32_t)((wn * 32 + ((lane >> 4) & 1) * 8 + (lane & 7)) * ROWB
                                     + ((lane >> 3) & 1) * 16);

    for (int c = 0; c < NC; c++) {
        const int buf = c & 1;
        if (c + 1 < NC) cp_wait<1>(); else cp_wait<0>();
        __syncthreads();

        const uint32_t s0   = sbase + buf * STAGE_B;
        const uint32_t sAhi = s0;
        const uint32_t sAlo = s0 + TILE_B;
        const uint32_t sB   = s0 + (NT - 1) * TILE_B;

        #pragma unroll
        for (int ks = 0; ks < 2; ks++) {
            const uint32_t kb = ks * 32;
            uint32_t ahi[4][4], alo[4][4], bt[2][4];
            #pragma unroll
            for (int mt = 0; mt < 4; mt++) {
                ldsm_x4(ahi[mt], sAhi + aOff + kb + mt * 16 * ROWB);
                if (SPLIT_A) ldsm_x4(alo[mt], sAlo + aOff + kb + mt * 16 * ROWB);
            }
            #pragma unroll
            for (int p = 0; p < 2; p++) {
                ldsm_x4(bt[p], sB + bOff + kb + p * 16 * ROWB);
            }
            #pragma unroll
            for (int mt = 0; mt < 4; mt++) {
                #pragma unroll
                for (int nt = 0; nt < 4; nt++) {
                    uint32_t* bh = &bt[nt >> 1][(nt & 1) * 2];
                    mma_fp16(acc[mt][nt], ahi[mt], bh);
                    if (SPLIT_A) mma_fp16(acc[mt][nt], alo[mt], bh);
                }
            }
        }
        __syncthreads();
        if (c + 2 < NC) load_stage(buf, c + 2);
    }

    // ---------------- epilogue: bias + relu + store ----------------
    #pragma unroll
    for (int nt = 0; nt < 4; nt++) {
        const int col = nOff + wn * 32 + nt * 8 + (lane & 3) * 2;
        const float bz0 = bias[col];
        const float bz1 = bias[col + 1];
        #pragma unroll
        for (int mt = 0; mt < 4; mt++) {
            const int row0 = cRow + wm * 64 + mt * 16 + (lane >> 2);
            float v0 = fmaxf(acc[mt][nt][0] + bz0, 0.0f);
            float v1 = fmaxf(acc[mt][nt][1] + bz1, 0.0f);
            float v2 = fmaxf(acc[mt][nt][2] + bz0, 0.0f);
            float v3 = fmaxf(acc[mt][nt][3] + bz1, 0.0f);
            if (FP16OUT) {
                *(uint32_t*)(outH + (size_t)row0 * NN + col) = pack_half2(v0, v1);
                *(uint32_t*)(outH + (size_t)(row0 + 8) * NN + col) = pack_half2(v2, v3);
            } else {
                *(float2*)(outF + (size_t)row0 * NN + col) = make_float2(v0, v1);
                *(float2*)(outF + (size_t)(row0 + 8) * NN + col) = make_float2(v2, v3);
            }
        }
    }
}

// ---------------------------------------------------------------------------
extern "C" void kernel_launch(void* const* d_in, const int* in_sizes, int n_in,
                              void* d_out, int out_size)
{
    const float* xyz1 = (const float*)d_in[0];
    const float* xyz2 = (const float*)d_in[1];
    const float* f1   = (const float*)d_in[2];
    const float* f2   = (const float*)d_in[3];
    const float* W1   = (const float*)d_in[4];
    const float* b1   = (const float*)d_in[5];
    const float* W2   = (const float*)d_in[6];
    const float* b2   = (const float*)d_in[7];
    float* out = (float*)d_out;

    __half *pXhi, *pXlo, *pH, *pW1, *pW2;
    cudaGetSymbolAddress((void**)&pXhi, g_Xhi);
    cudaGetSymbolAddress((void**)&pXlo, g_Xlo);
    cudaGetSymbolAddress((void**)&pH, g_H);
    cudaGetSymbolAddress((void**)&pW1, g_W1);
    cudaGetSymbolAddress((void**)&pW2, g_W2);

    const int g1_smem = 2 * 3 * 128 * 80;       // 61440 (split-A: 3 tiles/stage)
    const int g2_smem = 2 * 2 * 128 * 80;       // 40960 (1-pass: 2 tiles/stage)

    static bool attr_set = false;
    if (!attr_set) {
        cudaFuncSetAttribute(mma_gemm_kernel<H1V, CINV, true, true>,
            cudaFuncAttributeMaxDynamicSharedMemorySize, g1_smem);
        cudaFuncSetAttribute(mma_gemm_kernel<H2V, H1V, false, false>,
            cudaFuncAttributeMaxDynamicSharedMemorySize, g2_smem);
        attr_set = true;
    }

    knn_partial_kernel<<<dim3(N1V / 256, BATCH, SPL), 256>>>(xyz1, xyz2);
    prep_w_kernel<<<(CINV * H1V + H1V * H2V) / 256, 256>>>(W1, W2);
    knn_merge_kernel<<<NROWS / 256, 256>>>(xyz1);
    build_x_kernel<<<(NROWS * 32) / 256, 256>>>(f1, f2);

    mma_gemm_kernel<H1V, CINV, true, true>
        <<<dim3(NROWS / 128, H1V / 128), 256, g1_smem>>>(
            pXhi, pXlo, pW1, b1, nullptr, pH);
    mma_gemm_kernel<H2V, H1V, false, false>
        <<<dim3(NROWS / 128, H2V / 128), 256, g2_smem>>>(
            pH, nullptr, pW2, b2, out, nullptr);
}

// round 13
// speedup vs baseline: 1.0895x; 1.0895x over previous
#include <cuda_runtime.h>
#include <cuda_fp16.h>
#include <cstdint>

// Problem dims (fixed by the dataset)
#define BATCH 4
#define N1V   16384
#define N2V   4096
#define C1V   128
#define C2V   256
#define CINV  384      // C2 + C1 (concat order: [interp(256), features1(128)])
#define H1V   256
#define H2V   128
#define NROWS (BATCH * N1V)   // 65536

// ---------------- scratch (static device globals; no runtime allocation) ---
__device__ __align__(16) int     g_idx [NROWS * 3];
__device__ __align__(16) float   g_w   [NROWS * 3];
__device__ __align__(16) __half  g_Xhi [(size_t)NROWS * CINV];
__device__ __align__(16) __half  g_Xlo [(size_t)NROWS * CINV];
__device__ __align__(16) __half  g_H   [(size_t)NROWS * H1V];   // single fp16
__device__ __align__(16) __half  g_W1  [H1V * CINV];   // [h][c] K-major, fp16
__device__ __align__(16) __half  g_W2  [H2V * H1V];    // [o][h] K-major, fp16

// ---------------------------- PTX helpers (sm_80-era, legal on sm_103) -----
__device__ __forceinline__ uint32_t smem_u32(const void* p) {
    return (uint32_t)__cvta_generic_to_shared(p);
}
__device__ __forceinline__ void cp_async16(uint32_t dst, const void* src) {
    asm volatile("cp.async.ca.shared.global [%0], [%1], 16;"
                 :: "r"(dst), "l"(src) : "memory");
}
__device__ __forceinline__ void cp_commit() {
    asm volatile("cp.async.commit_group;" ::: "memory");
}
template<int N>
__device__ __forceinline__ void cp_wait() {
    asm volatile("cp.async.wait_group %0;" :: "n"(N) : "memory");
}
__device__ __forceinline__ void ldsm_x4(uint32_t* r, uint32_t addr) {
    asm volatile("ldmatrix.sync.aligned.m8n8.x4.shared.b16 {%0,%1,%2,%3}, [%4];"
                 : "=r"(r[0]), "=r"(r[1]), "=r"(r[2]), "=r"(r[3]) : "r"(addr));
}
__device__ __forceinline__ void mma_fp16(float* d, const uint32_t* a, const uint32_t* b) {
    asm volatile(
        "mma.sync.aligned.m16n8k16.row.col.f32.f16.f16.f32 "
        "{%0,%1,%2,%3}, {%4,%5,%6,%7}, {%8,%9}, {%0,%1,%2,%3};"
        : "+f"(d[0]), "+f"(d[1]), "+f"(d[2]), "+f"(d[3])
        : "r"(a[0]), "r"(a[1]), "r"(a[2]), "r"(a[3]), "r"(b[0]), "r"(b[1]));
}

// fp16 split helpers
__device__ __forceinline__ uint32_t pack_half2(float a, float b) {
    __half2 t = __floats2half2_rn(a, b);
    return *reinterpret_cast<uint32_t*>(&t);
}
__device__ __forceinline__ float h_round(float v) {
    return __half2float(__float2half_rn(v));
}

// ---------------------------------------------------------------------------
// Kernel 1: 3-NN over xyz2 via score s = 0.5|p|^2 - q.p  (argmin-equivalent).
// xyz2 cached as float4 (px,py,pz, 0.5|p|^2) in 64KB dynamic shared.
// BRANCHLESS top-3 insert: 3 FSETP + 10 SEL, no BSSY/BSYNC, so ptxas can
// software-pipeline the unrolled candidates across the LDS/FFMA latency.
// Semantics identical to the strict-< nested-if insert.
// ---------------------------------------------------------------------------
__global__ __launch_bounds__(256) void knn_kernel(
    const float* __restrict__ xyz1, const float* __restrict__ xyz2)
{
    extern __shared__ float4 s2[];   // N2V float4 = 64KB

    const int b = blockIdx.y;
    const float* p2 = xyz2 + (size_t)b * N2V * 3;
    for (int i = threadIdx.x; i < N2V; i += blockDim.x) {
        const float px = p2[3 * i + 0];
        const float py = p2[3 * i + 1];
        const float pz = p2[3 * i + 2];
        const float h  = 0.5f * fmaf(pz, pz, fmaf(py, py, px * px));
        s2[i] = make_float4(px, py, pz, h);
    }
    __syncthreads();

    const int n   = blockIdx.x * blockDim.x + threadIdx.x;
    const int row = b * N1V + n;
    const float x1 = xyz1[(size_t)row * 3 + 0];
    const float y1 = xyz1[(size_t)row * 3 + 1];
    const float z1 = xyz1[(size_t)row * 3 + 2];
    const float nqx = -x1, nqy = -y1, nqz = -z1;

    float t0 = 1e30f, t1 = 1e30f, t2 = 1e30f;
    int   i0 = 0,     i1 = 0,     i2 = 0;

    #pragma unroll 8
    for (int j = 0; j < N2V; j++) {
        const float4 p = s2[j];
        const float s = fmaf(nqx, p.x, fmaf(nqy, p.y, fmaf(nqz, p.z, p.w)));
        const bool c0 = s < t0;
        const bool c1 = s < t1;
        const bool c2 = s < t2;
        // shift-down insert, pure selects (exactly matches nested-if insert):
        t2 = c1 ? t1 : (c2 ? s : t2);
        i2 = c1 ? i1 : (c2 ? j : i2);
        t1 = c0 ? t0 : (c1 ? s : t1);
        i1 = c0 ? i0 : (c1 ? j : i1);
        t0 = c0 ? s : t0;
        i0 = c0 ? j : i0;
    }

    const float qq = fmaf(z1, z1, fmaf(y1, y1, x1 * x1));
    float d0 = fmaxf(fmaf(2.0f, t0, qq), 1e-10f);
    float d1 = fmaxf(fmaf(2.0f, t1, qq), 1e-10f);
    float d2 = fmaxf(fmaf(2.0f, t2, qq), 1e-10f);
    float w0 = 1.0f / d0, w1 = 1.0f / d1, w2 = 1.0f / d2;
    const float inv = 1.0f / (w0 + w1 + w2);

    g_idx[row * 3 + 0] = i0;
    g_idx[row * 3 + 1] = i1;
    g_idx[row * 3 + 2] = i2;
    g_w[row * 3 + 0] = w0 * inv;
    g_w[row * 3 + 1] = w1 * inv;
    g_w[row * 3 + 2] = w2 * inv;
}

// ---------------------------------------------------------------------------
// Kernel 2: build X as fp16 hi/lo split:  [interp(256) | features1(128)]
// One warp per row.
// ---------------------------------------------------------------------------
__global__ __launch_bounds__(256) void build_x_kernel(
    const float* __restrict__ f1, const float* __restrict__ f2)
{
    const int gtid = blockIdx.x * blockDim.x + threadIdx.x;
    const int row  = gtid >> 5;
    const int lane = gtid & 31;
    if (row >= NROWS) return;
    const int b = row >> 14;

    const int   i0 = g_idx[row * 3 + 0];
    const int   i1 = g_idx[row * 3 + 1];
    const int   i2 = g_idx[row * 3 + 2];
    const float w0 = g_w[row * 3 + 0];
    const float w1 = g_w[row * 3 + 1];
    const float w2 = g_w[row * 3 + 2];

    const float* fb = f2 + (size_t)b * N2V * C2V;
    const float* p0 = fb + (size_t)i0 * C2V;
    const float* p1 = fb + (size_t)i1 * C2V;
    const float* p2 = fb + (size_t)i2 * C2V;

    // interp: 8 cols per lane
    const int c0 = lane * 8;
    float v[8];
    {
        float4 a0 = *(const float4*)(p0 + c0), a1 = *(const float4*)(p0 + c0 + 4);
        float4 b0 = *(const float4*)(p1 + c0), b1 = *(const float4*)(p1 + c0 + 4);
        float4 cc0 = *(const float4*)(p2 + c0), cc1 = *(const float4*)(p2 + c0 + 4);
        const float* pa = (const float*)&a0;
        const float* pb = (const float*)&b0;
        const float* pc = (const float*)&cc0;
        #pragma unroll
        for (int j = 0; j < 4; j++)
            v[j] = fmaf(w2, pc[j], fmaf(w1, pb[j], w0 * pa[j]));
        pa = (const float*)&a1; pb = (const float*)&b1; pc = (const float*)&cc1;
        #pragma unroll
        for (int j = 0; j < 4; j++)
            v[4 + j] = fmaf(w2, pc[j], fmaf(w1, pb[j], w0 * pa[j]));
    }
    uint32_t hp[4], lp[4];
    #pragma unroll
    for (int j = 0; j < 4; j++) {
        float a = v[2 * j], bb = v[2 * j + 1];
        hp[j] = pack_half2(a, bb);
        lp[j] = pack_half2(a - h_round(a), bb - h_round(bb));
    }
    __half* xh = g_Xhi + (size_t)row * CINV;
    __half* xl = g_Xlo + (size_t)row * CINV;
    *(uint4*)(xh + c0) = make_uint4(hp[0], hp[1], hp[2], hp[3]);
    *(uint4*)(xl + c0) = make_uint4(lp[0], lp[1], lp[2], lp[3]);

    // features1: 4 cols per lane
    const float4 fv = *(const float4*)(f1 + (size_t)row * C1V + lane * 4);
    uint32_t h0 = pack_half2(fv.x, fv.y);
    uint32_t h1 = pack_half2(fv.z, fv.w);
    uint32_t l0 = pack_half2(fv.x - h_round(fv.x), fv.y - h_round(fv.y));
    uint32_t l1 = pack_half2(fv.z - h_round(fv.z), fv.w - h_round(fv.w));
    *(uint2*)(xh + C2V + lane * 4) = make_uint2(h0, h1);
    *(uint2*)(xl + C2V + lane * 4) = make_uint2(l0, l1);
}

// ---------------------------------------------------------------------------
// Kernel 2b: transpose W1 (384x256 -> [256][384]) and W2 (256x128 -> [128][256])
// to K-major fp16 (single precision level — B-side quantization ~3e-4 rel).
// ---------------------------------------------------------------------------
__global__ __launch_bounds__(256) void prep_w_kernel(
    const float* __restrict__ W1, const float* __restrict__ W2)
{
    const int idx = blockIdx.x * blockDim.x + threadIdx.x;
    if (idx < CINV * H1V) {
        const int c = idx >> 8;      // / 256
        const int h = idx & 255;
        g_W1[h * CINV + c] = __float2half_rn(W1[idx]);
    } else {
        const int j = idx - CINV * H1V;
        if (j < H1V * H2V) {
            const int c = j >> 7;    // / 128
            const int h = j & 127;
            g_W2[h * H1V + c] = __float2half_rn(W2[j]);
        }
    }
}

// ---------------------------------------------------------------------------
// mma.sync fp16 GEMM:  C[M,NN] = relu( A[M,KK] * B[NN,KK]^T + bias )
// SPLIT_A=true : 2-pass D += Ahi*B + Alo*B  (A hi/lo fp16 split)
// SPLIT_A=false: 1-pass D += A*B            (A single fp16)
// fp32 accumulators. CTA 128x128, BK=32, 8 warps (2m x 4n), warp tile 64x32,
// double-buffer cp.async (2 stages). SMEM rows padded to 40 halfs (80B).
// FP16OUT: write result as single fp16 (feeds GEMM2); else fp32.
// ---------------------------------------------------------------------------
template<int NN, int KK, bool SPLIT_A, bool FP16OUT>
__global__ __launch_bounds__(256) void mma_gemm_kernel(
    const __half* __restrict__ Ahi_g, const __half* __restrict__ Alo_g,
    const __half* __restrict__ B_g,
    const float* __restrict__ bias,
    float* __restrict__ outF, __half* __restrict__ outH)
{
    constexpr int BM = 128, BK = 32;
    constexpr int NC = KK / BK;
    constexpr int NT = SPLIT_A ? 3 : 2;       // tiles per stage
    constexpr int LDS_H = 40;                 // padded halfs per smem row
    constexpr int ROWB  = LDS_H * 2;          // 80 bytes
    constexpr int TILE_B = 128 * ROWB;        // 10240 bytes per tile
    constexpr int STAGE_B = NT * TILE_B;

    extern __shared__ char smem[];
    const uint32_t sbase = smem_u32(smem);

    const int tid  = threadIdx.x;
    const int wid  = tid >> 5;
    const int lane = tid & 31;
    const int wm   = wid & 1;          // 0..1  (m)
    const int wn   = wid >> 1;         // 0..3  (n)
    const int cRow = blockIdx.x * BM;
    const int nOff = blockIdx.y * 128;

    const __half* gA[NT];
    gA[0] = Ahi_g + (size_t)cRow * KK;
    if (SPLIT_A) {
        gA[1] = Alo_g + (size_t)cRow * KK;
        gA[NT - 1] = B_g + (size_t)nOff * KK;
    } else {
        gA[NT - 1] = B_g + (size_t)nOff * KK;
    }

    // stage loader: NT tiles x 128 rows x 32 halfs (64B = 4x16B per row)
    auto load_stage = [&](int buf, int c) {
        const uint32_t s0 = sbase + buf * STAGE_B;
        #pragma unroll
        for (int t = 0; t < NT; t++) {
            const __half* g = gA[t] + c * BK;
            const uint32_t st = s0 + t * TILE_B;
            #pragma unroll
            for (int i = 0; i < 2; i++) {
                const int idx = tid + i * 256;      // 0..511
                const int r   = idx >> 2;
                const int seg = idx & 3;
                cp_async16(st + r * ROWB + seg * 16, g + (size_t)r * KK + seg * 8);
            }
        }
        cp_commit();
    };

    float acc[4][4][4] = {};   // [mt][nt][4]

    load_stage(0, 0);
    if (NC > 1) load_stage(1, 1);

    // per-lane ldmatrix base offsets
    const uint32_t aOff = (uint32_t)((wm * 64 + (lane & 15)) * ROWB + (lane >> 4) * 16);
    const uint32_t bOff = (uint32_t)((wn * 32 + ((lane >> 4) & 1) * 8 + (lane & 7)) * ROWB
                                     + ((lane >> 3) & 1) * 16);

    for (int c = 0; c < NC; c++) {
        const int buf = c & 1;
        if (c + 1 < NC) cp_wait<1>(); else cp_wait<0>();
        __syncthreads();

        const uint32_t s0   = sbase + buf * STAGE_B;
        const uint32_t sAhi = s0;
        const uint32_t sAlo = s0 + TILE_B;
        const uint32_t sB   = s0 + (NT - 1) * TILE_B;

        #pragma unroll
        for (int ks = 0; ks < 2; ks++) {
            const uint32_t kb = ks * 32;
            uint32_t ahi[4][4], alo[4][4], bt[2][4];
            #pragma unroll
            for (int mt = 0; mt < 4; mt++) {
                ldsm_x4(ahi[mt], sAhi + aOff + kb + mt * 16 * ROWB);
                if (SPLIT_A) ldsm_x4(alo[mt], sAlo + aOff + kb + mt * 16 * ROWB);
            }
            #pragma unroll
            for (int p = 0; p < 2; p++) {
                ldsm_x4(bt[p], sB + bOff + kb + p * 16 * ROWB);
            }
            #pragma unroll
            for (int mt = 0; mt < 4; mt++) {
                #pragma unroll
                for (int nt = 0; nt < 4; nt++) {
                    uint32_t* bh = &bt[nt >> 1][(nt & 1) * 2];
                    mma_fp16(acc[mt][nt], ahi[mt], bh);
                    if (SPLIT_A) mma_fp16(acc[mt][nt], alo[mt], bh);
                }
            }
        }
        __syncthreads();
        if (c + 2 < NC) load_stage(buf, c + 2);
    }

    // ---------------- epilogue: bias + relu + store ----------------
    #pragma unroll
    for (int nt = 0; nt < 4; nt++) {
        const int col = nOff + wn * 32 + nt * 8 + (lane & 3) * 2;
        const float bz0 = bias[col];
        const float bz1 = bias[col + 1];
        #pragma unroll
        for (int mt = 0; mt < 4; mt++) {
            const int row0 = cRow + wm * 64 + mt * 16 + (lane >> 2);
            float v0 = fmaxf(acc[mt][nt][0] + bz0, 0.0f);
            float v1 = fmaxf(acc[mt][nt][1] + bz1, 0.0f);
            float v2 = fmaxf(acc[mt][nt][2] + bz0, 0.0f);
            float v3 = fmaxf(acc[mt][nt][3] + bz1, 0.0f);
            if (FP16OUT) {
                *(uint32_t*)(outH + (size_t)row0 * NN + col) = pack_half2(v0, v1);
                *(uint32_t*)(outH + (size_t)(row0 + 8) * NN + col) = pack_half2(v2, v3);
            } else {
                *(float2*)(outF + (size_t)row0 * NN + col) = make_float2(v0, v1);
                *(float2*)(outF + (size_t)(row0 + 8) * NN + col) = make_float2(v2, v3);
            }
        }
    }
}

// ---------------------------------------------------------------------------
extern "C" void kernel_launch(void* const* d_in, const int* in_sizes, int n_in,
                              void* d_out, int out_size)
{
    const float* xyz1 = (const float*)d_in[0];
    const float* xyz2 = (const float*)d_in[1];
    const float* f1   = (const float*)d_in[2];
    const float* f2   = (const float*)d_in[3];
    const float* W1   = (const float*)d_in[4];
    const float* b1   = (const float*)d_in[5];
    const float* W2   = (const float*)d_in[6];
    const float* b2   = (const float*)d_in[7];
    float* out = (float*)d_out;

    __half *pXhi, *pXlo, *pH, *pW1, *pW2;
    cudaGetSymbolAddress((void**)&pXhi, g_Xhi);
    cudaGetSymbolAddress((void**)&pXlo, g_Xlo);
    cudaGetSymbolAddress((void**)&pH, g_H);
    cudaGetSymbolAddress((void**)&pW1, g_W1);
    cudaGetSymbolAddress((void**)&pW2, g_W2);

    const int knn_smem = N2V * sizeof(float4);   // 64KB
    const int g1_smem  = 2 * 3 * 128 * 80;       // 61440 (split-A: 3 tiles/stage)
    const int g2_smem  = 2 * 2 * 128 * 80;       // 40960 (1-pass: 2 tiles/stage)

    static bool attr_set = false;
    if (!attr_set) {
        cudaFuncSetAttribute(knn_kernel,
            cudaFuncAttributeMaxDynamicSharedMemorySize, knn_smem);
        cudaFuncSetAttribute(mma_gemm_kernel<H1V, CINV, true, true>,
            cudaFuncAttributeMaxDynamicSharedMemorySize, g1_smem);
        cudaFuncSetAttribute(mma_gemm_kernel<H2V, H1V, false, false>,
            cudaFuncAttributeMaxDynamicSharedMemorySize, g2_smem);
        attr_set = true;
    }

    knn_kernel<<<dim3(N1V / 256, BATCH), 256, knn_smem>>>(xyz1, xyz2);
    prep_w_kernel<<<(CINV * H1V + H1V * H2V) / 256, 256>>>(W1, W2);
    build_x_kernel<<<(NROWS * 32) / 256, 256>>>(f1, f2);

    mma_gemm_kernel<H1V, CINV, true, true>
        <<<dim3(NROWS / 128, H1V / 128), 256, g1_smem>>>(
            pXhi, pXlo, pW1, b1, nullptr, pH);
    mma_gemm_kernel<H2V, H1V, false, false>
        <<<dim3(NROWS / 128, H2V / 128), 256, g2_smem>>>(
            pH, nullptr, pW2, b2, out, nullptr);
}

// round 17
// speedup vs baseline: 1.4444x; 1.3257x over previous
#include <cuda_runtime.h>
#include <cuda_fp16.h>
#include <cstdint>

// Problem dims (fixed by the dataset)
#define BATCH 4
#define N1V   16384
#define N2V   4096
#define C1V   128
#define C2V   256
#define CINV  384      // C2 + C1 (concat order: [interp(256), features1(128)])
#define H1V   256
#define H2V   128
#define NROWS (BATCH * N1V)   // 65536

// ---------------- scratch (static device globals; no runtime allocation) ---
__device__ __align__(16) int     g_idx [NROWS * 3];
__device__ __align__(16) float   g_w   [NROWS * 3];
__device__ __align__(16) __half  g_Xhi [(size_t)NROWS * CINV];
__device__ __align__(16) __half  g_Xlo [(size_t)NROWS * CINV];
__device__ __align__(16) __half  g_H   [(size_t)NROWS * H1V];   // single fp16
__device__ __align__(16) __half  g_W1  [H1V * CINV];   // [h][c] K-major, fp16
__device__ __align__(16) __half  g_W2  [H2V * H1V];    // [o][h] K-major, fp16

// ---------------------------- PTX helpers (sm_80-era, legal on sm_103) -----
__device__ __forceinline__ uint32_t smem_u32(const void* p) {
    return (uint32_t)__cvta_generic_to_shared(p);
}
__device__ __forceinline__ void cp_async16(uint32_t dst, const void* src) {
    asm volatile("cp.async.ca.shared.global [%0], [%1], 16;"
                 :: "r"(dst), "l"(src) : "memory");
}
__device__ __forceinline__ void cp_commit() {
    asm volatile("cp.async.commit_group;" ::: "memory");
}
template<int N>
__device__ __forceinline__ void cp_wait() {
    asm volatile("cp.async.wait_group %0;" :: "n"(N) : "memory");
}
__device__ __forceinline__ void ldsm_x4(uint32_t* r, uint32_t addr) {
    asm volatile("ldmatrix.sync.aligned.m8n8.x4.shared.b16 {%0,%1,%2,%3}, [%4];"
                 : "=r"(r[0]), "=r"(r[1]), "=r"(r[2]), "=r"(r[3]) : "r"(addr));
}
__device__ __forceinline__ void mma_fp16(float* d, const uint32_t* a, const uint32_t* b) {
    asm volatile(
        "mma.sync.aligned.m16n8k16.row.col.f32.f16.f16.f32 "
        "{%0,%1,%2,%3}, {%4,%5,%6,%7}, {%8,%9}, {%0,%1,%2,%3};"
        : "+f"(d[0]), "+f"(d[1]), "+f"(d[2]), "+f"(d[3])
        : "r"(a[0]), "r"(a[1]), "r"(a[2]), "r"(a[3]), "r"(b[0]), "r"(b[1]));
}

// fp16 split helpers
__device__ __forceinline__ uint32_t pack_half2(float a, float b) {
    __half2 t = __floats2half2_rn(a, b);
    return *reinterpret_cast<uint32_t*>(&t);
}
__device__ __forceinline__ float h_round(float v) {
    return __half2float(__float2half_rn(v));
}

// top-3 insert (ascending scores, strict <)
#define INS3(s, jj, S0, S1, S2, I0, I1, I2)                      \
    if ((s) < (S2)) {                                            \
        if ((s) < (S1)) {                                        \
            (S2) = (S1); (I2) = (I1);                            \
            if ((s) < (S0)) { (S1) = (S0); (I1) = (I0);          \
                              (S0) = (s);  (I0) = (jj); }        \
            else            { (S1) = (s);  (I1) = (jj); }        \
        } else { (S2) = (s); (I2) = (jj); }                      \
    }

// packed f32x2 score for a candidate PAIR:
//   s0 = h0 - qx*x0 - qy*y0 - qz*z0,  s1 likewise (IEEE fp32 per lane)
__device__ __forceinline__ void score2(
    unsigned long long nx, unsigned long long ny, unsigned long long nz,
    const float4 A, const float4 B, float& s0, float& s1)
{
    asm("{\n\t"
        ".reg .b64 x2, y2, z2, h2, t;\n\t"
        "mov.b64 x2, {%2, %3};\n\t"
        "mov.b64 y2, {%4, %5};\n\t"
        "mov.b64 z2, {%6, %7};\n\t"
        "mov.b64 h2, {%8, %9};\n\t"
        "fma.rn.f32x2 t, %10, x2, h2;\n\t"
        "fma.rn.f32x2 t, %11, y2, t;\n\t"
        "fma.rn.f32x2 t, %12, z2, t;\n\t"
        "mov.b64 {%0, %1}, t;\n\t"
        "}"
        : "=f"(s0), "=f"(s1)
        : "f"(A.x), "f"(A.y), "f"(A.z), "f"(A.w),
          "f"(B.x), "f"(B.y), "f"(B.z), "f"(B.w),
          "l"(nx), "l"(ny), "l"(nz));
}

// ---------------------------------------------------------------------------
// Kernel 1: 3-NN over xyz2 via score s = 0.5|p|^2 - q.p  (argmin-equivalent).
// Candidate PAIRS packed SoA in 64KB shared: sA[j]=(x0,x1,y0,y1),
// sB[j]=(z0,z1,h0,h1). Fast path per pair: 2 LDS.128 + 3 FFMA2 + FMNMX +
// FSETP + BRA (~5 slots/candidate). Rare path replays strict-< inserts in
// index order -> selection identical to sequential scan.
// ---------------------------------------------------------------------------
__global__ __launch_bounds__(256) void knn_kernel(
    const float* __restrict__ xyz1, const float* __restrict__ xyz2)
{
    extern __shared__ float4 smk[];   // sA[2048] | sB[2048] = 64KB
    float4* sA = smk;
    float4* sB = smk + (N2V / 2);

    const int b = blockIdx.y;
    const float* p2 = xyz2 + (size_t)b * N2V * 3;
    for (int i = threadIdx.x; i < N2V / 2; i += blockDim.x) {
        const float* c = p2 + 6 * i;
        const float x0 = c[0], y0 = c[1], z0 = c[2];
        const float x1 = c[3], y1 = c[4], z1 = c[5];
        const float h0 = 0.5f * fmaf(z0, z0, fmaf(y0, y0, x0 * x0));
        const float h1 = 0.5f * fmaf(z1, z1, fmaf(y1, y1, x1 * x1));
        sA[i] = make_float4(x0, x1, y0, y1);
        sB[i] = make_float4(z0, z1, h0, h1);
    }
    __syncthreads();

    const int n   = blockIdx.x * blockDim.x + threadIdx.x;
    const int row = b * N1V + n;
    const float x1q = xyz1[(size_t)row * 3 + 0];
    const float y1q = xyz1[(size_t)row * 3 + 1];
    const float z1q = xyz1[(size_t)row * 3 + 2];
    const float nqx = -x1q, nqy = -y1q, nqz = -z1q;

    unsigned long long nx, ny, nz;
    asm("mov.b64 %0, {%1, %1};" : "=l"(nx) : "f"(nqx));
    asm("mov.b64 %0, {%1, %1};" : "=l"(ny) : "f"(nqy));
    asm("mov.b64 %0, {%1, %1};" : "=l"(nz) : "f"(nqz));

    float t0 = 1e30f, t1 = 1e30f, t2 = 1e30f;
    int   i0 = 0,     i1 = 0,     i2 = 0;

    #pragma unroll 8
    for (int j = 0; j < N2V / 2; j++) {
        const float4 A = sA[j];
        const float4 B = sB[j];
        float s0, s1;
        score2(nx, ny, nz, A, B, s0, s1);
        const float smin = fminf(s0, s1);
        if (smin < t2) {
            INS3(s0, 2 * j,     t0, t1, t2, i0, i1, i2);
            INS3(s1, 2 * j + 1, t0, t1, t2, i0, i1, i2);
        }
    }

    const float qq = fmaf(z1q, z1q, fmaf(y1q, y1q, x1q * x1q));
    float d0 = fmaxf(fmaf(2.0f, t0, qq), 1e-10f);
    float d1 = fmaxf(fmaf(2.0f, t1, qq), 1e-10f);
    float d2 = fmaxf(fmaf(2.0f, t2, qq), 1e-10f);
    float w0 = 1.0f / d0, w1 = 1.0f / d1, w2 = 1.0f / d2;
    const float inv = 1.0f / (w0 + w1 + w2);

    g_idx[row * 3 + 0] = i0;
    g_idx[row * 3 + 1] = i1;
    g_idx[row * 3 + 2] = i2;
    g_w[row * 3 + 0] = w0 * inv;
    g_w[row * 3 + 1] = w1 * inv;
    g_w[row * 3 + 2] = w2 * inv;
}

// ---------------------------------------------------------------------------
// Kernel 2: build X as fp16 hi/lo split:  [interp(256) | features1(128)]
// One warp per row.
// ---------------------------------------------------------------------------
__global__ __launch_bounds__(256) void build_x_kernel(
    const float* __restrict__ f1, const float* __restrict__ f2)
{
    const int gtid = blockIdx.x * blockDim.x + threadIdx.x;
    const int row  = gtid >> 5;
    const int lane = gtid & 31;
    if (row >= NROWS) return;
    const int b = row >> 14;

    const int   i0 = g_idx[row * 3 + 0];
    const int   i1 = g_idx[row * 3 + 1];
    const int   i2 = g_idx[row * 3 + 2];
    const float w0 = g_w[row * 3 + 0];
    const float w1 = g_w[row * 3 + 1];
    const float w2 = g_w[row * 3 + 2];

    const float* fb = f2 + (size_t)b * N2V * C2V;
    const float* p0 = fb + (size_t)i0 * C2V;
    const float* p1 = fb + (size_t)i1 * C2V;
    const float* p2 = fb + (size_t)i2 * C2V;

    // interp: 8 cols per lane
    const int c0 = lane * 8;
    float v[8];
    {
        float4 a0 = *(const float4*)(p0 + c0), a1 = *(const float4*)(p0 + c0 + 4);
        float4 b0 = *(const float4*)(p1 + c0), b1 = *(const float4*)(p1 + c0 + 4);
        float4 cc0 = *(const float4*)(p2 + c0), cc1 = *(const float4*)(p2 + c0 + 4);
        const float* pa = (const float*)&a0;
        const float* pb = (const float*)&b0;
        const float* pc = (const float*)&cc0;
        #pragma unroll
        for (int j = 0; j < 4; j++)
            v[j] = fmaf(w2, pc[j], fmaf(w1, pb[j], w0 * pa[j]));
        pa = (const float*)&a1; pb = (const float*)&b1; pc = (const float*)&cc1;
        #pragma unroll
        for (int j = 0; j < 4; j++)
            v[4 + j] = fmaf(w2, pc[j], fmaf(w1, pb[j], w0 * pa[j]));
    }
    uint32_t hp[4], lp[4];
    #pragma unroll
    for (int j = 0; j < 4; j++) {
        float a = v[2 * j], bb = v[2 * j + 1];
        hp[j] = pack_half2(a, bb);
        lp[j] = pack_half2(a - h_round(a), bb - h_round(bb));
    }
    __half* xh = g_Xhi + (size_t)row * CINV;
    __half* xl = g_Xlo + (size_t)row * CINV;
    *(uint4*)(xh + c0) = make_uint4(hp[0], hp[1], hp[2], hp[3]);
    *(uint4*)(xl + c0) = make_uint4(lp[0], lp[1], lp[2], lp[3]);

    // features1: 4 cols per lane
    const float4 fv = *(const float4*)(f1 + (size_t)row * C1V + lane * 4);
    uint32_t h0 = pack_half2(fv.x, fv.y);
    uint32_t h1 = pack_half2(fv.z, fv.w);
    uint32_t l0 = pack_half2(fv.x - h_round(fv.x), fv.y - h_round(fv.y));
    uint32_t l1 = pack_half2(fv.z - h_round(fv.z), fv.w - h_round(fv.w));
    *(uint2*)(xh + C2V + lane * 4) = make_uint2(h0, h1);
    *(uint2*)(xl + C2V + lane * 4) = make_uint2(l0, l1);
}

// ---------------------------------------------------------------------------
// Kernel 2b: transpose W1 (384x256 -> [256][384]) and W2 (256x128 -> [128][256])
// to K-major fp16 (single precision level — B-side quantization ~3e-4 rel).
// ---------------------------------------------------------------------------
__global__ __launch_bounds__(256) void prep_w_kernel(
    const float* __restrict__ W1, const float* __restrict__ W2)
{
    const int idx = blockIdx.x * blockDim.x + threadIdx.x;
    if (idx < CINV * H1V) {
        const int c = idx >> 8;      // / 256
        const int h = idx & 255;
        g_W1[h * CINV + c] = __float2half_rn(W1[idx]);
    } else {
        const int j = idx - CINV * H1V;
        if (j < H1V * H2V) {
            const int c = j >> 7;    // / 128
            const int h = j & 127;
            g_W2[h * H1V + c] = __float2half_rn(W2[j]);
        }
    }
}

// ---------------------------------------------------------------------------
// mma.sync fp16 GEMM:  C[M,NN] = relu( A[M,KK] * B[NN,KK]^T + bias )
// SPLIT_A=true : 2-pass D += Ahi*B + Alo*B  (A hi/lo fp16 split)
// SPLIT_A=false: 1-pass D += A*B            (A single fp16)
// fp32 accumulators. CTA 128x128, BK=32, 8 warps (2m x 4n), warp tile 64x32,
// double-buffer cp.async (2 stages). SMEM rows padded to 40 halfs (80B).
// FP16OUT: write result as single fp16 (feeds GEMM2); else fp32.
// ---------------------------------------------------------------------------
template<int NN, int KK, bool SPLIT_A, bool FP16OUT>
__global__ __launch_bounds__(256) void mma_gemm_kernel(
    const __half* __restrict__ Ahi_g, const __half* __restrict__ Alo_g,
    const __half* __restrict__ B_g,
    const float* __restrict__ bias,
    float* __restrict__ outF, __half* __restrict__ outH)
{
    constexpr int BM = 128, BK = 32;
    constexpr int NC = KK / BK;
    constexpr int NT = SPLIT_A ? 3 : 2;       // tiles per stage
    constexpr int LDS_H = 40;                 // padded halfs per smem row
    constexpr int ROWB  = LDS_H * 2;          // 80 bytes
    constexpr int TILE_B = 128 * ROWB;        // 10240 bytes per tile
    constexpr int STAGE_B = NT * TILE_B;

    extern __shared__ char smem[];
    const uint32_t sbase = smem_u32(smem);

    const int tid  = threadIdx.x;
    const int wid  = tid >> 5;
    const int lane = tid & 31;
    const int wm   = wid & 1;          // 0..1  (m)
    const int wn   = wid >> 1;         // 0..3  (n)
    const int cRow = blockIdx.x * BM;
    const int nOff = blockIdx.y * 128;

    const __half* gA[NT];
    gA[0] = Ahi_g + (size_t)cRow * KK;
    if (SPLIT_A) {
        gA[1] = Alo_g + (size_t)cRow * KK;
        gA[NT - 1] = B_g + (size_t)nOff * KK;
    } else {
        gA[NT - 1] = B_g + (size_t)nOff * KK;
    }

    // stage loader: NT tiles x 128 rows x 32 halfs (64B = 4x16B per row)
    auto load_stage = [&](int buf, int c) {
        const uint32_t s0 = sbase + buf * STAGE_B;
        #pragma unroll
        for (int t = 0; t < NT; t++) {
            const __half* g = gA[t] + c * BK;
            const uint32_t st = s0 + t * TILE_B;
            #pragma unroll
            for (int i = 0; i < 2; i++) {
                const int idx = tid + i * 256;      // 0..511
                const int r   = idx >> 2;
                const int seg = idx & 3;
                cp_async16(st + r * ROWB + seg * 16, g + (size_t)r * KK + seg * 8);
            }
        }
        cp_commit();
    };

    float acc[4][4][4] = {};   // [mt][nt][4]

    load_stage(0, 0);
    if (NC > 1) load_stage(1, 1);

    // per-lane ldmatrix base offsets
    const uint32_t aOff = (uint32_t)((wm * 64 + (lane & 15)) * ROWB + (lane >> 4) * 16);
    const uint32_t bOff = (uint32_t)((wn * 32 + ((lane >> 4) & 1) * 8 + (lane & 7)) * ROWB
                                     + ((lane >> 3) & 1) * 16);

    for (int c = 0; c < NC; c++) {
        const int buf = c & 1;
        if (c + 1 < NC) cp_wait<1>(); else cp_wait<0>();
        __syncthreads();

        const uint32_t s0   = sbase + buf * STAGE_B;
        const uint32_t sAhi = s0;
        const uint32_t sAlo = s0 + TILE_B;
        const uint32_t sB   = s0 + (NT - 1) * TILE_B;

        #pragma unroll
        for (int ks = 0; ks < 2; ks++) {
            const uint32_t kb = ks * 32;
            uint32_t ahi[4][4], alo[4][4], bt[2][4];
            #pragma unroll
            for (int mt = 0; mt < 4; mt++) {
                ldsm_x4(ahi[mt], sAhi + aOff + kb + mt * 16 * ROWB);
                if (SPLIT_A) ldsm_x4(alo[mt], sAlo + aOff + kb + mt * 16 * ROWB);
            }
            #pragma unroll
            for (int p = 0; p < 2; p++) {
                ldsm_x4(bt[p], sB + bOff + kb + p * 16 * ROWB);
            }
            #pragma unroll
            for (int mt = 0; mt < 4; mt++) {
                #pragma unroll
                for (int nt = 0; nt < 4; nt++) {
                    uint32_t* bh = &bt[nt >> 1][(nt & 1) * 2];
                    mma_fp16(acc[mt][nt], ahi[mt], bh);
                    if (SPLIT_A) mma_fp16(acc[mt][nt], alo[mt], bh);
                }
            }
        }
        __syncthreads();
        if (c + 2 < NC) load_stage(buf, c + 2);
    }

    // ---------------- epilogue: bias + relu + store ----------------
    #pragma unroll
    for (int nt = 0; nt < 4; nt++) {
        const int col = nOff + wn * 32 + nt * 8 + (lane & 3) * 2;
        const float bz0 = bias[col];
        const float bz1 = bias[col + 1];
        #pragma unroll
        for (int mt = 0; mt < 4; mt++) {
            const int row0 = cRow + wm * 64 + mt * 16 + (lane >> 2);
            float v0 = fmaxf(acc[mt][nt][0] + bz0, 0.0f);
            float v1 = fmaxf(acc[mt][nt][1] + bz1, 0.0f);
            float v2 = fmaxf(acc[mt][nt][2] + bz0, 0.0f);
            float v3 = fmaxf(acc[mt][nt][3] + bz1, 0.0f);
            if (FP16OUT) {
                *(uint32_t*)(outH + (size_t)row0 * NN + col) = pack_half2(v0, v1);
                *(uint32_t*)(outH + (size_t)(row0 + 8) * NN + col) = pack_half2(v2, v3);
            } else {
                *(float2*)(outF + (size_t)row0 * NN + col) = make_float2(v0, v1);
                *(float2*)(outF + (size_t)(row0 + 8) * NN + col) = make_float2(v2, v3);
            }
        }
    }
}

// ---------------------------------------------------------------------------
extern "C" void kernel_launch(void* const* d_in, const int* in_sizes, int n_in,
                              void* d_out, int out_size)
{
    const float* xyz1 = (const float*)d_in[0];
    const float* xyz2 = (const float*)d_in[1];
    const float* f1   = (const float*)d_in[2];
    const float* f2   = (const float*)d_in[3];
    const float* W1   = (const float*)d_in[4];
    const float* b1   = (const float*)d_in[5];
    const float* W2   = (const float*)d_in[6];
    const float* b2   = (const float*)d_in[7];
    float* out = (float*)d_out;

    __half *pXhi, *pXlo, *pH, *pW1, *pW2;
    cudaGetSymbolAddress((void**)&pXhi, g_Xhi);
    cudaGetSymbolAddress((void**)&pXlo, g_Xlo);
    cudaGetSymbolAddress((void**)&pH, g_H);
    cudaGetSymbolAddress((void**)&pW1, g_W1);
    cudaGetSymbolAddress((void**)&pW2, g_W2);

    const int knn_smem = N2V * 16;               // 64KB (sA + sB pair SoA)
    const int g1_smem  = 2 * 3 * 128 * 80;       // 61440 (split-A: 3 tiles/stage)
    const int g2_smem  = 2 * 2 * 128 * 80;       // 40960 (1-pass: 2 tiles/stage)

    static bool attr_set = false;
    if (!attr_set) {
        cudaFuncSetAttribute(knn_kernel,
            cudaFuncAttributeMaxDynamicSharedMemorySize, knn_smem);
        cudaFuncSetAttribute(mma_gemm_kernel<H1V, CINV, true, true>,
            cudaFuncAttributeMaxDynamicSharedMemorySize, g1_smem);
        cudaFuncSetAttribute(mma_gemm_kernel<H2V, H1V, false, false>,
            cudaFuncAttributeMaxDynamicSharedMemorySize, g2_smem);
        attr_set = true;
    }

    knn_kernel<<<dim3(N1V / 256, BATCH), 256, knn_smem>>>(xyz1, xyz2);
    prep_w_kernel<<<(CINV * H1V + H1V * H2V) / 256, 256>>>(W1, W2);
    build_x_kernel<<<(NROWS * 32) / 256, 256>>>(f1, f2);

    mma_gemm_kernel<H1V, CINV, true, true>
        <<<dim3(NROWS / 128, H1V / 128), 256, g1_smem>>>(
            pXhi, pXlo, pW1, b1, nullptr, pH);
    mma_gemm_kernel<H2V, H1V, false, false>
        <<<dim3(NROWS / 128, H2V / 128), 256, g2_smem>>>(
            pH, nullptr, pW2, b2, out, nullptr);
}